// round 3
// baseline (speedup 1.0000x reference)
#include <cuda_runtime.h>
#include <cuda_bf16.h>

// Problem constants
#define BSZ   512
#define NNODE 22
#define INDIM 128
#define HID   256
#define MROWS (BSZ * NNODE)   // 11264

// Scratch (device global: no allocation allowed)
__device__ float g_hs[BSZ * HID];            // segment sum over 22 nodes

// ---------------------------------------------------------------------------
// K1: fused GEMM1 + inline We1 fold + 22-node segment reduce.
//   h[m] = relu(x[m] @ (We1[:128]+We1[128:]) + be1);  hs[b] = sum_{a<22} h[b*22+a]
// BM=88 rows = exactly 4 groups of 22.  TM=11 -> each thread's rows lie in
// exactly one group.  grid (4, 128), block 128.
// ---------------------------------------------------------------------------
__global__ __launch_bounds__(128)
void gemm1_fused(const float* __restrict__ x,
                 const float* __restrict__ We1,
                 const float* __restrict__ be1) {
    constexpr int BM = 88, BN = 64, BK = 16, TM = 11, TN = 4;

    __shared__ float As[BK][BM + 1];
    __shared__ float Bs[BK][BN];
    __shared__ float red[4][16][TN];

    const int tid  = threadIdx.x;
    const int tCol = tid & 15;        // 16 col-threads
    const int tRow = tid >> 4;        // 8 row-threads
    const int cCol = blockIdx.x;      // N tile (4)
    const int cRow = blockIdx.y;      // M tile (128)

    const float* Ab = x + (size_t)cRow * BM * INDIM;
    const float* Bb = We1 + cCol * BN;            // top half; +128*HID = bottom

    const int aCol  = tid & 15;       // k within slab
    const int aRow0 = tid >> 4;       // row start, stride 8
    const int bCol  = tid & 63;
    const int bRow0 = tid >> 6;       // stride 2

    float acc[TM][TN];
#pragma unroll
    for (int i = 0; i < TM; i++)
#pragma unroll
        for (int j = 0; j < TN; j++) acc[i][j] = 0.0f;

    for (int k0 = 0; k0 < INDIM; k0 += BK) {
#pragma unroll
        for (int t = 0; t < 11; t++) {
            int r = aRow0 + 8 * t;
            As[aCol][r] = Ab[(size_t)r * INDIM + k0 + aCol];
        }
#pragma unroll
        for (int t = 0; t < 8; t++) {
            int r = bRow0 + 2 * t;
            // inline fold: We1[k][c] + We1[k+128][c]
            Bs[r][bCol] = Bb[(size_t)(k0 + r) * HID + bCol]
                        + Bb[(size_t)(k0 + r + INDIM) * HID + bCol];
        }
        __syncthreads();

#pragma unroll
        for (int kk = 0; kk < BK; kk++) {
            float rM[TM], rN[TN];
#pragma unroll
            for (int i = 0; i < TM; i++) rM[i] = As[kk][tRow * TM + i];
#pragma unroll
            for (int j = 0; j < TN; j++) rN[j] = Bs[kk][tCol * TN + j];
#pragma unroll
            for (int i = 0; i < TM; i++)
#pragma unroll
                for (int j = 0; j < TN; j++)
                    acc[i][j] = fmaf(rM[i], rN[j], acc[i][j]);
        }
        __syncthreads();
    }

    // Epilogue: relu+bias per row, then partial sum of this thread's 11 rows
    float part[TN];
#pragma unroll
    for (int j = 0; j < TN; j++) {
        const float b = be1[cCol * BN + tCol * TN + j];
        float s = 0.0f;
#pragma unroll
        for (int i = 0; i < TM; i++)
            s += fmaxf(acc[i][j] + b, 0.0f);
        part[j] = s;
    }

    const int g = tRow >> 1;
    if (tRow & 1) {
#pragma unroll
        for (int j = 0; j < TN; j++) red[g][tCol][j] = part[j];
    }
    __syncthreads();
    if (!(tRow & 1)) {
#pragma unroll
        for (int j = 0; j < TN; j++) {
            float s = part[j] + red[g][tCol][j];
            g_hs[(size_t)(cRow * 4 + g) * HID + cCol * BN + tCol * TN + j] = s;
        }
    }
}

// ---------------------------------------------------------------------------
// K2: fused 3-layer tail + 22-way broadcast output.
// One block = 8 batch rows (R=8), 256 threads: thread c owns output column c.
// Weights read DIRECTLY from the original row-major layout: at step k, thread
// c loads W[k*256 + c] -> consecutive addresses across the warp (coalesced).
// grid 64 blocks.
// ---------------------------------------------------------------------------
#define RTAIL 8

__device__ __forceinline__ void layer_dot_direct(const float* __restrict__ W,
                                                 int c,
                                                 const float (*src)[HID],
                                                 float v[RTAIL]) {
    float a[RTAIL];
#pragma unroll
    for (int r = 0; r < RTAIL; r++) a[r] = 0.0f;

#pragma unroll 4
    for (int k4 = 0; k4 < HID / 4; k4++) {
        // 4 independent coalesced weight loads (MLP)
        float w0 = W[(size_t)(4 * k4 + 0) * HID + c];
        float w1 = W[(size_t)(4 * k4 + 1) * HID + c];
        float w2 = W[(size_t)(4 * k4 + 2) * HID + c];
        float w3 = W[(size_t)(4 * k4 + 3) * HID + c];
#pragma unroll
        for (int r = 0; r < RTAIL; r++) {
            float4 s = *(const float4*)&src[r][4 * k4];   // smem broadcast
            a[r] = fmaf(w0, s.x, a[r]);
            a[r] = fmaf(w1, s.y, a[r]);
            a[r] = fmaf(w2, s.z, a[r]);
            a[r] = fmaf(w3, s.w, a[r]);
        }
    }
#pragma unroll
    for (int r = 0; r < RTAIL; r++) v[r] = a[r];
}

__global__ __launch_bounds__(256)
void fused_tail(const float* __restrict__ We2,
                const float* __restrict__ be2,
                const float* __restrict__ Wn1,
                const float* __restrict__ bn1,
                const float* __restrict__ Wn2,
                const float* __restrict__ bn2,
                float* __restrict__ out) {
    __shared__ float act[2][RTAIL][HID];

    const int c  = threadIdx.x;
    const int b0 = blockIdx.x * RTAIL;

#pragma unroll
    for (int r = 0; r < RTAIL; r++)
        act[0][r][c] = g_hs[(size_t)(b0 + r) * HID + c];
    __syncthreads();

    float v[RTAIL];

    // Layer 0: S = hs @ We2 + 22*be2   (no relu)
    layer_dot_direct(We2, c, act[0], v);
    {
        const float b = 22.0f * be2[c];
#pragma unroll
        for (int r = 0; r < RTAIL; r++) act[1][r][c] = v[r] + b;
    }
    __syncthreads();

    // Layer 1: t = relu(S @ Wn1 + bn1)
    layer_dot_direct(Wn1, c, act[1], v);
    {
        const float b = bn1[c];
#pragma unroll
        for (int r = 0; r < RTAIL; r++) act[0][r][c] = fmaxf(v[r] + b, 0.0f);
    }
    __syncthreads();

    // Layer 2: out = t @ Wn2 + bn2, broadcast to all 22 nodes
    layer_dot_direct(Wn2, c, act[0], v);
    {
        const float b = bn2[c];
#pragma unroll
        for (int r = 0; r < RTAIL; r++) {
            const float o = v[r] + b;
            size_t base = ((size_t)(b0 + r) * NNODE) * HID + c;
#pragma unroll
            for (int i = 0; i < NNODE; i++)
                out[base + (size_t)i * HID] = o;
        }
    }
}

// ---------------------------------------------------------------------------
extern "C" void kernel_launch(void* const* d_in, const int* in_sizes, int n_in,
                              void* d_out, int out_size) {
    const float* x   = (const float*)d_in[0];
    const float* We1 = (const float*)d_in[1];
    const float* be1 = (const float*)d_in[2];
    const float* We2 = (const float*)d_in[3];
    const float* be2 = (const float*)d_in[4];
    const float* Wn1 = (const float*)d_in[5];
    const float* bn1 = (const float*)d_in[6];
    const float* Wn2 = (const float*)d_in[7];
    const float* bn2 = (const float*)d_in[8];
    float* out = (float*)d_out;

    // K1: fused GEMM1 (+We1 fold) + segment reduce -> g_hs [512 x 256]
    {
        dim3 grid(HID / 64, MROWS / 88);   // (4, 128)
        gemm1_fused<<<grid, 128>>>(x, We1, be1);
    }

    // K2: 3-layer tail + broadcast -> out
    fused_tail<<<BSZ / RTAIL, HID>>>(We2, be2, Wn1, bn1, Wn2, bn2, out);
}

// round 4
// speedup vs baseline: 1.3809x; 1.3809x over previous
#include <cuda_runtime.h>
#include <cuda_bf16.h>

// Problem constants
#define BSZ   512
#define NNODE 22
#define INDIM 128
#define HID   256
#define MROWS (BSZ * NNODE)   // 11264

// Scratch (device globals: no allocation allowed)
__device__ float g_hs[BSZ * HID];   // segment sum over 22 nodes
__device__ float g_S [BSZ * HID];   // layer-0 output
__device__ float g_t [BSZ * HID];   // layer-1 output

// ---------------------------------------------------------------------------
// K1: fused GEMM1 + inline We1 fold + 22-node segment reduce.
//   h[m] = relu(x[m] @ (We1[:128]+We1[128:]) + be1);  hs[b] = sum_{a<22} h[b*22+a]
// BM=88 rows = exactly 4 groups of 22.  grid (4, 128), block 128.
// ---------------------------------------------------------------------------
__global__ __launch_bounds__(128)
void gemm1_fused(const float* __restrict__ x,
                 const float* __restrict__ We1,
                 const float* __restrict__ be1) {
    constexpr int BM = 88, BN = 64, BK = 16, TM = 11, TN = 4;

    __shared__ float As[BK][BM + 1];
    __shared__ float Bs[BK][BN];
    __shared__ float red[4][16][TN];

    const int tid  = threadIdx.x;
    const int tCol = tid & 15;
    const int tRow = tid >> 4;
    const int cCol = blockIdx.x;
    const int cRow = blockIdx.y;

    const float* Ab = x + (size_t)cRow * BM * INDIM;
    const float* Bb = We1 + cCol * BN;

    const int aCol  = tid & 15;
    const int aRow0 = tid >> 4;
    const int bCol  = tid & 63;
    const int bRow0 = tid >> 6;

    float acc[TM][TN];
#pragma unroll
    for (int i = 0; i < TM; i++)
#pragma unroll
        for (int j = 0; j < TN; j++) acc[i][j] = 0.0f;

    for (int k0 = 0; k0 < INDIM; k0 += BK) {
#pragma unroll
        for (int t = 0; t < 11; t++) {
            int r = aRow0 + 8 * t;
            As[aCol][r] = Ab[(size_t)r * INDIM + k0 + aCol];
        }
#pragma unroll
        for (int t = 0; t < 8; t++) {
            int r = bRow0 + 2 * t;
            Bs[r][bCol] = Bb[(size_t)(k0 + r) * HID + bCol]
                        + Bb[(size_t)(k0 + r + INDIM) * HID + bCol];
        }
        __syncthreads();

#pragma unroll
        for (int kk = 0; kk < BK; kk++) {
            float rM[TM], rN[TN];
#pragma unroll
            for (int i = 0; i < TM; i++) rM[i] = As[kk][tRow * TM + i];
#pragma unroll
            for (int j = 0; j < TN; j++) rN[j] = Bs[kk][tCol * TN + j];
#pragma unroll
            for (int i = 0; i < TM; i++)
#pragma unroll
                for (int j = 0; j < TN; j++)
                    acc[i][j] = fmaf(rM[i], rN[j], acc[i][j]);
        }
        __syncthreads();
    }

    float part[TN];
#pragma unroll
    for (int j = 0; j < TN; j++) {
        const float b = be1[cCol * BN + tCol * TN + j];
        float s = 0.0f;
#pragma unroll
        for (int i = 0; i < TM; i++)
            s += fmaxf(acc[i][j] + b, 0.0f);
        part[j] = s;
    }

    const int g = tRow >> 1;
    if (tRow & 1) {
#pragma unroll
        for (int j = 0; j < TN; j++) red[g][tCol][j] = part[j];
    }
    __syncthreads();
    if (!(tRow & 1)) {
#pragma unroll
        for (int j = 0; j < TN; j++) {
            float s = part[j] + red[g][tCol][j];
            g_hs[(size_t)(cRow * 4 + g) * HID + cCol * BN + tCol * TN + j] = s;
        }
    }
}

// ---------------------------------------------------------------------------
// Tail GEMM: C[512,256] = act(A[512,256] @ W[256,256] + biasScale*bias)
// BM=32, BN=32, BK=32, 128 threads, TM=2 x TN=4.
// grid (8, 16) = 128 blocks -> ~full chip. Register prefetch double-buffer.
// BCAST: final layer broadcasts each row to 22 node rows.
// ---------------------------------------------------------------------------
template <bool RELU, bool BCAST>
__global__ __launch_bounds__(128)
void gemm256(const float* __restrict__ A,
             const float* __restrict__ W,
             const float* __restrict__ bias,
             float biasScale,
             float* __restrict__ C) {
    __shared__ float As[32][33];   // [k][m], pad 33 -> conflict-free T-stores
    __shared__ float Bs[32][32];   // [k][n]

    const int tid  = threadIdx.x;
    const int tCol = tid & 7;      // 8 col-threads * 4 cols
    const int tRow = tid >> 3;     // 16 row-threads * 2 rows
    const int m0   = blockIdx.y * 32;
    const int n0   = blockIdx.x * 32;

    // loader indices: lr = row/k-row (two passes +16), lk4 = float4 k/n offset
    const int lr  = tid >> 3;          // 0..15
    const int lk4 = (tid & 7) * 4;     // 0,4,..,28

    const float* Abase = A + (size_t)(m0 + lr) * HID;
    const float* Wbase = W + (size_t)lr * HID + n0;

    float4 a0, a1, b0, b1;
    // prefetch slab 0
    a0 = *(const float4*)&Abase[lk4];
    a1 = *(const float4*)&Abase[16 * HID + lk4];
    b0 = *(const float4*)&Wbase[lk4];
    b1 = *(const float4*)&Wbase[16 * HID + lk4];

    float acc[2][4];
#pragma unroll
    for (int i = 0; i < 2; i++)
#pragma unroll
        for (int j = 0; j < 4; j++) acc[i][j] = 0.0f;

#pragma unroll
    for (int s = 0; s < 8; s++) {
        // store current slab to smem
        As[lk4 + 0][lr]      = a0.x;
        As[lk4 + 1][lr]      = a0.y;
        As[lk4 + 2][lr]      = a0.z;
        As[lk4 + 3][lr]      = a0.w;
        As[lk4 + 0][lr + 16] = a1.x;
        As[lk4 + 1][lr + 16] = a1.y;
        As[lk4 + 2][lr + 16] = a1.z;
        As[lk4 + 3][lr + 16] = a1.w;
        *(float4*)&Bs[lr][lk4]      = b0;
        *(float4*)&Bs[lr + 16][lk4] = b1;
        __syncthreads();

        // prefetch next slab
        if (s < 7) {
            const int k0 = (s + 1) * 32;
            a0 = *(const float4*)&Abase[k0 + lk4];
            a1 = *(const float4*)&Abase[16 * HID + k0 + lk4];
            b0 = *(const float4*)&Wbase[(size_t)k0 * HID + lk4];
            b1 = *(const float4*)&Wbase[(size_t)(k0 + 16) * HID + lk4];
        }

        // compute
#pragma unroll
        for (int kk = 0; kk < 32; kk++) {
            const float rm0 = As[kk][2 * tRow];
            const float rm1 = As[kk][2 * tRow + 1];
            const float4 rn = *(const float4*)&Bs[kk][4 * tCol];
            acc[0][0] = fmaf(rm0, rn.x, acc[0][0]);
            acc[0][1] = fmaf(rm0, rn.y, acc[0][1]);
            acc[0][2] = fmaf(rm0, rn.z, acc[0][2]);
            acc[0][3] = fmaf(rm0, rn.w, acc[0][3]);
            acc[1][0] = fmaf(rm1, rn.x, acc[1][0]);
            acc[1][1] = fmaf(rm1, rn.y, acc[1][1]);
            acc[1][2] = fmaf(rm1, rn.z, acc[1][2]);
            acc[1][3] = fmaf(rm1, rn.w, acc[1][3]);
        }
        __syncthreads();
    }

    // epilogue
    const float4 bv = *(const float4*)&bias[n0 + 4 * tCol];
#pragma unroll
    for (int i = 0; i < 2; i++) {
        float4 v;
        v.x = acc[i][0] + biasScale * bv.x;
        v.y = acc[i][1] + biasScale * bv.y;
        v.z = acc[i][2] + biasScale * bv.z;
        v.w = acc[i][3] + biasScale * bv.w;
        if (RELU) {
            v.x = fmaxf(v.x, 0.0f); v.y = fmaxf(v.y, 0.0f);
            v.z = fmaxf(v.z, 0.0f); v.w = fmaxf(v.w, 0.0f);
        }
        const int row = m0 + 2 * tRow + i;
        const int col = n0 + 4 * tCol;
        if (!BCAST) {
            *(float4*)&C[(size_t)row * HID + col] = v;
        } else {
            size_t base = ((size_t)row * NNODE) * HID + col;
#pragma unroll
            for (int p = 0; p < NNODE; p++)
                *(float4*)&C[base + (size_t)p * HID] = v;
        }
    }
}

// ---------------------------------------------------------------------------
extern "C" void kernel_launch(void* const* d_in, const int* in_sizes, int n_in,
                              void* d_out, int out_size) {
    const float* x   = (const float*)d_in[0];
    const float* We1 = (const float*)d_in[1];
    const float* be1 = (const float*)d_in[2];
    const float* We2 = (const float*)d_in[3];
    const float* be2 = (const float*)d_in[4];
    const float* Wn1 = (const float*)d_in[5];
    const float* bn1 = (const float*)d_in[6];
    const float* Wn2 = (const float*)d_in[7];
    const float* bn2 = (const float*)d_in[8];
    float* out = (float*)d_out;

    float *phs, *pS, *pt;
    cudaGetSymbolAddress((void**)&phs, g_hs);
    cudaGetSymbolAddress((void**)&pS,  g_S);
    cudaGetSymbolAddress((void**)&pt,  g_t);

    // K1: fused GEMM1 (+We1 fold) + segment reduce -> g_hs [512 x 256]
    {
        dim3 grid(HID / 64, MROWS / 88);   // (4, 128)
        gemm1_fused<<<grid, 128>>>(x, We1, be1);
    }

    dim3 tg(HID / 32, BSZ / 32);           // (8, 16) = 128 blocks

    // L0: S = hs @ We2 + 22*be2
    gemm256<false, false><<<tg, 128>>>(phs, We2, be2, (float)NNODE, pS);
    // L1: t = relu(S @ Wn1 + bn1)
    gemm256<true,  false><<<tg, 128>>>(pS,  Wn1, bn1, 1.0f, pt);
    // L2: out = t @ Wn2 + bn2, broadcast over 22 nodes
    gemm256<false, true ><<<tg, 128>>>(pt,  Wn2, bn2, 1.0f, out);
}

// round 5
// speedup vs baseline: 1.6263x; 1.1777x over previous
#include <cuda_runtime.h>
#include <cuda_bf16.h>
#include <cstdint>

// Problem constants
#define BSZ   512
#define NNODE 22
#define INDIM 128
#define HID   256
#define MROWS (BSZ * NNODE)   // 11264

// Scratch (device globals: no allocation allowed)
__device__ float g_hs[BSZ * HID];   // segment sum over 22 nodes
__device__ float g_S [BSZ * HID];   // layer-0 output
__device__ float g_t [BSZ * HID];   // layer-1 output

// ---------------------------------------------------------------------------
// K1: fused GEMM1 + inline We1 fold + 22-node segment reduce. (unchanged)
// ---------------------------------------------------------------------------
__global__ __launch_bounds__(128)
void gemm1_fused(const float* __restrict__ x,
                 const float* __restrict__ We1,
                 const float* __restrict__ be1) {
    constexpr int BM = 88, BN = 64, BK = 16, TM = 11, TN = 4;

    __shared__ float As[BK][BM + 1];
    __shared__ float Bs[BK][BN];
    __shared__ float red[4][16][TN];

    const int tid  = threadIdx.x;
    const int tCol = tid & 15;
    const int tRow = tid >> 4;
    const int cCol = blockIdx.x;
    const int cRow = blockIdx.y;

    const float* Ab = x + (size_t)cRow * BM * INDIM;
    const float* Bb = We1 + cCol * BN;

    const int aCol  = tid & 15;
    const int aRow0 = tid >> 4;
    const int bCol  = tid & 63;
    const int bRow0 = tid >> 6;

    float acc[TM][TN];
#pragma unroll
    for (int i = 0; i < TM; i++)
#pragma unroll
        for (int j = 0; j < TN; j++) acc[i][j] = 0.0f;

    for (int k0 = 0; k0 < INDIM; k0 += BK) {
#pragma unroll
        for (int t = 0; t < 11; t++) {
            int r = aRow0 + 8 * t;
            As[aCol][r] = Ab[(size_t)r * INDIM + k0 + aCol];
        }
#pragma unroll
        for (int t = 0; t < 8; t++) {
            int r = bRow0 + 2 * t;
            Bs[r][bCol] = Bb[(size_t)(k0 + r) * HID + bCol]
                        + Bb[(size_t)(k0 + r + INDIM) * HID + bCol];
        }
        __syncthreads();

#pragma unroll
        for (int kk = 0; kk < BK; kk++) {
            float rM[TM], rN[TN];
#pragma unroll
            for (int i = 0; i < TM; i++) rM[i] = As[kk][tRow * TM + i];
#pragma unroll
            for (int j = 0; j < TN; j++) rN[j] = Bs[kk][tCol * TN + j];
#pragma unroll
            for (int i = 0; i < TM; i++)
#pragma unroll
                for (int j = 0; j < TN; j++)
                    acc[i][j] = fmaf(rM[i], rN[j], acc[i][j]);
        }
        __syncthreads();
    }

    float part[TN];
#pragma unroll
    for (int j = 0; j < TN; j++) {
        const float b = be1[cCol * BN + tCol * TN + j];
        float s = 0.0f;
#pragma unroll
        for (int i = 0; i < TM; i++)
            s += fmaxf(acc[i][j] + b, 0.0f);
        part[j] = s;
    }

    const int g = tRow >> 1;
    if (tRow & 1) {
#pragma unroll
        for (int j = 0; j < TN; j++) red[g][tCol][j] = part[j];
    }
    __syncthreads();
    if (!(tRow & 1)) {
#pragma unroll
        for (int j = 0; j < TN; j++) {
            float s = part[j] + red[g][tCol][j];
            g_hs[(size_t)(cRow * 4 + g) * HID + cCol * BN + tCol * TN + j] = s;
        }
    }
}

// ---------------------------------------------------------------------------
// Tensor-core tail: C[512,256] = act(A @ W + biasScale*bias) per layer.
// mma.sync.m16n8k8.tf32 with 3xTF32 split (fp32-grade accuracy).
// Block = 16x32 tile, 128 threads, warp split-K (64 each) + smem reduce.
// Grid (8, 32) = 256 blocks.
// ---------------------------------------------------------------------------
__device__ __forceinline__ void f32_to_tf32x2(float v, uint32_t& hi, uint32_t& lo) {
    asm("cvt.rna.tf32.f32 %0, %1;" : "=r"(hi) : "f"(v));
    float r = v - __uint_as_float(hi);
    asm("cvt.rna.tf32.f32 %0, %1;" : "=r"(lo) : "f"(r));
}

__device__ __forceinline__ void mma_tf32(float* d, const uint32_t* a,
                                         uint32_t b0, uint32_t b1) {
    asm volatile(
        "mma.sync.aligned.m16n8k8.row.col.f32.tf32.tf32.f32 "
        "{%0,%1,%2,%3}, {%4,%5,%6,%7}, {%8,%9}, {%0,%1,%2,%3};"
        : "+f"(d[0]), "+f"(d[1]), "+f"(d[2]), "+f"(d[3])
        : "r"(a[0]), "r"(a[1]), "r"(a[2]), "r"(a[3]), "r"(b0), "r"(b1));
}

template <bool RELU, bool BCAST>
__global__ __launch_bounds__(128)
void tail_mma(const float* __restrict__ A,
              const float* __restrict__ W,
              const float* __restrict__ bias,
              float biasScale,
              float* __restrict__ C) {
    __shared__ float As[16][256];      // swizzled: col k stored at k ^ (4*(m&7))
    __shared__ float Bst[32 * 256];    // B^T swizzled; reused as reduce scratch

    float (*Bs)[256] = reinterpret_cast<float(*)[256]>(Bst);

    const int t  = threadIdx.x;
    const int w  = t >> 5;       // warp 0..3 -> k-slice
    const int l  = t & 31;
    const int g  = l >> 2;       // 0..7
    const int t4 = l & 3;        // 0..3
    const int m0 = blockIdx.y * 16;
    const int n0 = blockIdx.x * 32;

    // ---- Stage A tile [16 x 256] (coalesced float4, XOR swizzle) ----
#pragma unroll
    for (int i = 0; i < 8; i++) {
        int flat = i * 512 + t * 4;
        int m = flat >> 8, k = flat & 255;
        float4 v = *(const float4*)&A[(size_t)(m0 + m) * 256 + k];
        *(float4*)&As[m][k ^ (4 * (m & 7))] = v;
    }
    // ---- Stage B^T tile [32 x 256]: Bs[n][k] = W[k][n0+n], swizzled ----
    {
        const int nl = t & 31;
        const int kb = (t >> 5) * 64;
        const int sw = 4 * (nl & 7);
#pragma unroll 8
        for (int kk = 0; kk < 64; kk++) {
            int k = kb + kk;
            Bs[nl][k ^ sw] = W[(size_t)k * 256 + n0 + nl];
        }
    }
    __syncthreads();

    // ---- Compute: warp w covers k in [64w, 64w+64) ----
    float acc[4][4];
#pragma unroll
    for (int nt = 0; nt < 4; nt++)
#pragma unroll
        for (int j = 0; j < 4; j++) acc[nt][j] = 0.0f;

    const int sw = 4 * g;   // rows g, g+8, nt*8+g all share (row&7)==g

#pragma unroll
    for (int c = 0; c < 8; c++) {
        const int k0 = w * 64 + c * 8;
        const int ka = (k0 + t4) ^ sw;
        const int kb2 = (k0 + t4 + 4) ^ sw;

        uint32_t ah[4], al[4];
        f32_to_tf32x2(As[g][ka],      ah[0], al[0]);
        f32_to_tf32x2(As[g + 8][ka],  ah[1], al[1]);
        f32_to_tf32x2(As[g][kb2],     ah[2], al[2]);
        f32_to_tf32x2(As[g + 8][kb2], ah[3], al[3]);

#pragma unroll
        for (int nt = 0; nt < 4; nt++) {
            uint32_t bh0, bl0, bh1, bl1;
            f32_to_tf32x2(Bs[nt * 8 + g][ka],  bh0, bl0);
            f32_to_tf32x2(Bs[nt * 8 + g][kb2], bh1, bl1);
            mma_tf32(acc[nt], ah, bh0, bh1);   // hi*hi
            mma_tf32(acc[nt], ah, bl0, bl1);   // hi*lo
            mma_tf32(acc[nt], al, bh0, bh1);   // lo*hi
        }
    }
    __syncthreads();   // all warps done reading Bs -> safe to reuse as scratch

    // ---- Cross-warp split-K reduce via smem ----
    typedef float RedT[16][33];
    RedT* red = reinterpret_cast<RedT*>(Bst);
#pragma unroll
    for (int nt = 0; nt < 4; nt++) {
        const int col = nt * 8 + 2 * t4;
        red[w][g][col]         = acc[nt][0];
        red[w][g][col + 1]     = acc[nt][1];
        red[w][g + 8][col]     = acc[nt][2];
        red[w][g + 8][col + 1] = acc[nt][3];
    }
    __syncthreads();

    // ---- Epilogue: thread owns 4 consecutive cols of one row ----
    const int row = t >> 3;
    const int cb  = (t & 7) * 4;
    float v[4];
#pragma unroll
    for (int j = 0; j < 4; j++)
        v[j] = red[0][row][cb + j] + red[1][row][cb + j]
             + red[2][row][cb + j] + red[3][row][cb + j];

    const float4 bv = *(const float4*)&bias[n0 + cb];
    float4 o;
    o.x = v[0] + biasScale * bv.x;
    o.y = v[1] + biasScale * bv.y;
    o.z = v[2] + biasScale * bv.z;
    o.w = v[3] + biasScale * bv.w;
    if (RELU) {
        o.x = fmaxf(o.x, 0.0f); o.y = fmaxf(o.y, 0.0f);
        o.z = fmaxf(o.z, 0.0f); o.w = fmaxf(o.w, 0.0f);
    }

    const int rowg = m0 + row;
    const int colg = n0 + cb;
    if (!BCAST) {
        *(float4*)&C[(size_t)rowg * 256 + colg] = o;
    } else {
        size_t base = ((size_t)rowg * NNODE) * 256 + colg;
#pragma unroll
        for (int p = 0; p < NNODE; p++)
            *(float4*)&C[base + (size_t)p * 256] = o;
    }
}

// ---------------------------------------------------------------------------
extern "C" void kernel_launch(void* const* d_in, const int* in_sizes, int n_in,
                              void* d_out, int out_size) {
    const float* x   = (const float*)d_in[0];
    const float* We1 = (const float*)d_in[1];
    const float* be1 = (const float*)d_in[2];
    const float* We2 = (const float*)d_in[3];
    const float* be2 = (const float*)d_in[4];
    const float* Wn1 = (const float*)d_in[5];
    const float* bn1 = (const float*)d_in[6];
    const float* Wn2 = (const float*)d_in[7];
    const float* bn2 = (const float*)d_in[8];
    float* out = (float*)d_out;

    float *phs, *pS, *pt;
    cudaGetSymbolAddress((void**)&phs, g_hs);
    cudaGetSymbolAddress((void**)&pS,  g_S);
    cudaGetSymbolAddress((void**)&pt,  g_t);

    // K1: fused GEMM1 (+We1 fold) + segment reduce -> g_hs [512 x 256]
    {
        dim3 grid(HID / 64, MROWS / 88);   // (4, 128)
        gemm1_fused<<<grid, 128>>>(x, We1, be1);
    }

    dim3 tg(HID / 32, BSZ / 16);           // (8, 32) = 256 blocks

    // L0: S = hs @ We2 + 22*be2
    tail_mma<false, false><<<tg, 128>>>(phs, We2, be2, (float)NNODE, pS);
    // L1: t = relu(S @ Wn1 + bn1)
    tail_mma<true,  false><<<tg, 128>>>(pS,  Wn1, bn1, 1.0f, pt);
    // L2: out = t @ Wn2 + bn2, broadcast over 22 nodes
    tail_mma<false, true ><<<tg, 128>>>(pt,  Wn2, bn2, 1.0f, out);
}